// round 1
// baseline (speedup 1.0000x reference)
#include <cuda_runtime.h>
#include <math.h>

#define NMAX 50000
#define EMAX 800000

// ---------------- scratch (static device memory, no allocation) ----------------
__device__ float g_dinv[NMAX];                    // deg -> dinv in place
__device__ float g_h1[(size_t)NMAX * 128];        // x @ W1
__device__ float g_agg1[(size_t)NMAX * 128];      // layer-1 aggregation
__device__ float g_h2[(size_t)NMAX * 16];         // relu(agg1+b1) @ W2
__device__ int   g_src[EMAX];
__device__ int   g_dst[EMAX];
__device__ int   g_is64;

// ---------------- dtype detection: int64 vs int32 edge_index ----------------
__global__ void k_detect(const int* __restrict__ ei) {
    int is64 = 1;
    for (int i = 1; i < 512; i += 2)
        if (ei[i] != 0) { is64 = 0; break; }
    g_is64 = is64;
}

__global__ void k_convert(const int* __restrict__ ei, int E) {
    int e = blockIdx.x * blockDim.x + threadIdx.x;
    if (e >= E) return;
    if (g_is64) { g_src[e] = ei[2 * e]; g_dst[e] = ei[2 * E + 2 * e]; }
    else        { g_src[e] = ei[e];     g_dst[e] = ei[E + e]; }
}

// ---------------- degree / normalization ----------------
__global__ void k_deg_init(int n) {
    int i = blockIdx.x * blockDim.x + threadIdx.x;
    if (i < n) g_dinv[i] = 1.0f;   // self-loop contributes 1 to degree
}

__global__ void k_deg_accum(int E) {
    int e = blockIdx.x * blockDim.x + threadIdx.x;
    if (e < E) atomicAdd(&g_dinv[g_dst[e]], 1.0f);
}

__global__ void k_dinv(int n) {
    int i = blockIdx.x * blockDim.x + threadIdx.x;
    if (i < n) g_dinv[i] = rsqrtf(fmaxf(g_dinv[i], 1.0f));
}

// ---------------- GEMM1: h1 = x @ W1  (x:[n,128], W1:[128,128]) ----------------
// Block = 128 threads (one output column each), 32 rows per block.
// W1 streamed through smem in two 64-row halves; 32 fp32 accumulators/thread.
__global__ __launch_bounds__(128) void k_gemm1(const float* __restrict__ x,
                                               const float* __restrict__ W,
                                               int n) {
    __shared__ float ws[64 * 128];   // 32 KB: one K-half of W1
    __shared__ float xs[32][64];     // 8 KB: 32 rows x 64 K
    int col  = threadIdx.x;
    int row0 = blockIdx.x * 32;
    float acc[32];
#pragma unroll
    for (int r = 0; r < 32; ++r) acc[r] = 0.0f;

    for (int kh = 0; kh < 2; ++kh) {
        __syncthreads();
        for (int i = col; i < 64 * 128; i += 128) ws[i] = W[kh * 64 * 128 + i];
        for (int i = col; i < 32 * 64; i += 128) {
            int r = i >> 6, k = i & 63;
            int gr = row0 + r;
            xs[r][k] = (gr < n) ? x[(size_t)gr * 128 + kh * 64 + k] : 0.0f;
        }
        __syncthreads();
        for (int k = 0; k < 64; ++k) {
            float w = ws[k * 128 + col];
#pragma unroll
            for (int r = 0; r < 32; ++r) acc[r] += xs[r][k] * w;
        }
    }
#pragma unroll
    for (int r = 0; r < 32; ++r) {
        int gr = row0 + r;
        if (gr < n) g_h1[(size_t)gr * 128 + col] = acc[r];
    }
}

// ---------------- vector atomic add (sm_90+): 4 floats in one L2 reduction ----------------
__device__ __forceinline__ void red_add_v4(float* addr, float a, float b, float c, float d) {
    asm volatile("red.global.add.v4.f32 [%0], {%1,%2,%3,%4};"
                 :: "l"(addr), "f"(a), "f"(b), "f"(c), "f"(d) : "memory");
}

// agg1 = self-loop term: h1[i] * dinv[i]^2
__global__ void k_selfinit1(int n) {
    int idx = blockIdx.x * blockDim.x + threadIdx.x;   // n*32 threads, 4 floats each
    if (idx >= n * 32) return;
    int i = idx >> 5, c = (idx & 31) << 2;
    float di = g_dinv[i];
    float w  = di * di;
    float4 v = *(const float4*)(g_h1 + (size_t)i * 128 + c);
    float4 o = make_float4(v.x * w, v.y * w, v.z * w, v.w * w);
    *(float4*)(g_agg1 + (size_t)i * 128 + c) = o;
}

// Layer-1 scatter: one warp per edge (32 lanes x float4 = 128 floats)
__global__ void k_scatter1(int E) {
    int idx = blockIdx.x * blockDim.x + threadIdx.x;   // E*32 threads
    int e = idx >> 5;
    if (e >= E) return;
    int c = (idx & 31) << 2;
    int s = g_src[e], d = g_dst[e];
    float w = g_dinv[s] * g_dinv[d];
    float4 v = *(const float4*)(g_h1 + (size_t)s * 128 + c);
    red_add_v4(g_agg1 + (size_t)d * 128 + c, v.x * w, v.y * w, v.z * w, v.w * w);
}

// ---------------- Layer 2: h2 = relu(agg1 + b1) @ W2  (W2:[128,16]) ----------------
__global__ __launch_bounds__(128) void k_relu_gemm2(const float* __restrict__ b1,
                                                    const float* __restrict__ W2,
                                                    int n) {
    __shared__ float w2s[128 * 16];  // 8 KB
    __shared__ float rows[8][128];   // 4 KB
    int tid  = threadIdx.x;
    int row0 = blockIdx.x * 8;
    for (int i = tid; i < 2048; i += 128) w2s[i] = W2[i];
    float bias = b1[tid];
#pragma unroll
    for (int r = 0; r < 8; ++r) {
        int gr = row0 + r;
        rows[r][tid] = (gr < n) ? fmaxf(g_agg1[(size_t)gr * 128 + tid] + bias, 0.0f) : 0.0f;
    }
    __syncthreads();
    int r = tid >> 4, c = tid & 15;
    float acc = 0.0f;
#pragma unroll 8
    for (int k = 0; k < 128; ++k) acc += rows[r][k] * w2s[k * 16 + c];
    int gr = row0 + r;
    if (gr < n) g_h2[(size_t)gr * 16 + c] = acc;
}

// out = self-loop term: h2[i] * dinv[i]^2
__global__ void k_selfinit2(float* __restrict__ out, int n) {
    int idx = blockIdx.x * blockDim.x + threadIdx.x;   // n*4 threads, 4 floats each
    if (idx >= n * 4) return;
    int i = idx >> 2, c = (idx & 3) << 2;
    float di = g_dinv[i];
    float w  = di * di;
    float4 v = *(const float4*)(g_h2 + (size_t)i * 16 + c);
    float4 o = make_float4(v.x * w, v.y * w, v.z * w, v.w * w);
    *(float4*)(out + (size_t)i * 16 + c) = o;
}

// Layer-2 scatter: 4 lanes per edge (4 x float4 = 16 floats)
__global__ void k_scatter2(float* __restrict__ out, int E) {
    int idx = blockIdx.x * blockDim.x + threadIdx.x;   // E*4 threads
    int e = idx >> 2;
    if (e >= E) return;
    int c = (idx & 3) << 2;
    int s = g_src[e], d = g_dst[e];
    float w = g_dinv[s] * g_dinv[d];
    float4 v = *(const float4*)(g_h2 + (size_t)s * 16 + c);
    red_add_v4(out + (size_t)d * 16 + c, v.x * w, v.y * w, v.z * w, v.w * w);
}

// ---------------- +b2 and log_softmax over 16 classes, in place ----------------
__global__ void k_lsm(float* __restrict__ out, const float* __restrict__ b2, int n) {
    int i = blockIdx.x * blockDim.x + threadIdx.x;
    if (i >= n) return;
    float v[16];
    float4* p = (float4*)(out + (size_t)i * 16);
#pragma unroll
    for (int j = 0; j < 4; ++j) {
        float4 t = p[j];
        v[4 * j + 0] = t.x + __ldg(b2 + 4 * j + 0);
        v[4 * j + 1] = t.y + __ldg(b2 + 4 * j + 1);
        v[4 * j + 2] = t.z + __ldg(b2 + 4 * j + 2);
        v[4 * j + 3] = t.w + __ldg(b2 + 4 * j + 3);
    }
    float m = v[0];
#pragma unroll
    for (int j = 1; j < 16; ++j) m = fmaxf(m, v[j]);
    float sum = 0.0f;
#pragma unroll
    for (int j = 0; j < 16; ++j) sum += expf(v[j] - m);
    float l = m + logf(sum);
#pragma unroll
    for (int j = 0; j < 4; ++j) {
        float4 o = make_float4(v[4 * j + 0] - l, v[4 * j + 1] - l,
                               v[4 * j + 2] - l, v[4 * j + 3] - l);
        p[j] = o;
    }
}

// ---------------- launch ----------------
extern "C" void kernel_launch(void* const* d_in, const int* in_sizes, int n_in,
                              void* d_out, int out_size) {
    const float* x  = (const float*)d_in[0];
    const int*   ei = (const int*)d_in[1];
    const float* W1 = (const float*)d_in[2];
    const float* b1 = (const float*)d_in[3];
    const float* W2 = (const float*)d_in[4];
    const float* b2 = (const float*)d_in[5];
    float* out = (float*)d_out;

    int n = in_sizes[0] / 128;
    int E = in_sizes[1] / 2;

    k_detect   <<<1, 1>>>(ei);
    k_convert  <<<(E + 255) / 256, 256>>>(ei, E);
    k_deg_init <<<(n + 255) / 256, 256>>>(n);
    k_deg_accum<<<(E + 255) / 256, 256>>>(E);
    k_dinv     <<<(n + 255) / 256, 256>>>(n);

    k_gemm1    <<<(n + 31) / 32, 128>>>(x, W1, n);
    k_selfinit1<<<(n * 32 + 255) / 256, 256>>>(n);
    k_scatter1 <<<(E * 32 + 255) / 256, 256>>>(E);

    k_relu_gemm2<<<(n + 7) / 8, 128>>>(b1, W2, n);
    k_selfinit2 <<<(n * 4 + 255) / 256, 256>>>(out, n);
    k_scatter2  <<<(E * 4 + 255) / 256, 256>>>(out, E);

    k_lsm       <<<(n + 255) / 256, 256>>>(out, b2, n);
}